// round 15
// baseline (speedup 1.0000x reference)
#include <cuda_runtime.h>
#include <math.h>

// Problem constants
#define TT    4096
#define BB    32
#define HH    512
#define HB    (HH * BB)            // 16384 floats per step
#define NCTA  128                  // persistent CTAs, all wave-1 resident
#define UNITS 4                    // hidden units per CTA
#define ROWS  16                   // gate rows per CTA (4 gates x 4 units)
#define NTHR  512                  // 16 warps
#define NSEG  16                   // k-segments per row (one per warp)
#define NGRP  16                   // barrier groups (8 CTAs each)
#define CTR_STRIDE 64              // 256B between counters -> distinct LTS lines

// Dynamic SMEM layout (floats)
#define PART_FLOATS (ROWS * NSEG * BB)          // 8192 floats = 32KB per buffer
#define SMEM_W2     (HH * ROWS * 2)             // duplicated weights: 64KB
#define SMEM_FLOATS (SMEM_W2 + 2 * PART_FLOATS + 128)
#define SMEM_BYTES  (SMEM_FLOATS * 4)           // ~131.5KB

// Inter-step hidden state [t][j][b] (b fastest). Distinct buffer per step
// => one-way producer/consumer sync, no anti-dependency.
__device__ float g_h[(size_t)TT * HB];   // 256 MB static scratch
// 16 cumulative group counters (group g = CTAs 8g..8g+7), padded 256B apart.
// PROVEN primitives only: red.release.gpu.add publish + ld.acquire.gpu poll.
__device__ __align__(256) unsigned g_ctr16[NGRP * CTR_STRIDE];

__global__ void init_kernel() { g_ctr16[threadIdx.x] = 0u; }  // 1024 threads

// Packed f32x2 FMA (Blackwell packed fp32 pipe).
__device__ __forceinline__ void fma2(unsigned long long& d,
                                     unsigned long long a,
                                     unsigned long long b) {
    asm("fma.rn.f32x2 %0, %1, %2, %0;" : "+l"(d) : "l"(a), "l"(b));
}

// Sigmoid via __expf (proven R2..R14). tanhf kept exactly as in R8 (fast
// variants were neutral-to-negative in R14; isolate the mainloop change).
__device__ __forceinline__ float sig_f(float x) {
    return __fdividef(1.0f, 1.0f + __expf(-x));
}

__global__ void __launch_bounds__(NTHR)
lstm_kernel(const float* __restrict__ x0,     // (T,B,1)
            const float* __restrict__ W_ih,   // (4H,1)
            const float* __restrict__ W_hh,   // (4H,H) row-major
            const float* __restrict__ b_ih,   // (4H)
            const float* __restrict__ b_hh)   // (4H)
{
    extern __shared__ float sm[];
    float* W2   = sm;                        // [k][r] duplicated pairs
    float* part = sm + SMEM_W2;              // 2 x [r][seg][b]
    float* x0s  = part + 2 * PART_FLOATS;    // 2 x 32 (double-buffered)
    float* wih  = x0s + 64;                  // 16
    float* bsum = wih + 16;                  // 16

    const int tid  = threadIdx.x;
    const int lane = tid & 31;
    const int w    = tid >> 5;           // warp 0..15 = k-segment
    const int q    = lane >> 3;          // row-quad 0..3: rows 4q..4q+3
    const int p    = lane & 7;           // batch-quad -> batches 4p..4p+3
    const int kbeg = w * 32;             // 32 k's per warp
    const int j0   = blockIdx.x * UNITS;
    // Counter this warp CONSUMES: group producing units [32w, 32w+32).
    const unsigned* cons_ctr = g_ctr16 + w * CTR_STRIDE;
    // Counter this CTA PRODUCES into: group blockIdx.x>>3.
    unsigned* prod_ctr = g_ctr16 + (blockIdx.x >> 3) * CTR_STRIDE;

    // Stage W_hh slice, k-major, duplicated pairs: W2[(k*16+r)*2 + {0,1}] = w.
    for (int idx = tid; idx < ROWS * HH; idx += NTHR) {
        int r = idx & 15, k = idx >> 4;
        int grow = (r >> 2) * HH + j0 + (r & 3);   // gate*512 + j0 + unit
        float wv = W_hh[(size_t)grow * HH + k];
        W2[(k * ROWS + r) * 2 + 0] = wv;
        W2[(k * ROWS + r) * 2 + 1] = wv;
    }
    if (tid < ROWS) {
        int grow = (tid >> 2) * HH + j0 + (tid & 3);
        wih[tid]  = W_ih[grow];
        bsum[tid] = b_ih[grow] + b_hh[grow];
    }
    if (w == 14) x0s[lane] = x0[lane];           // x0 for t=0
    __syncthreads();

    float c_reg = 0.0f;     // epilogue threads (tid<128): unit w, batch lane
    float xnext = 0.0f;

    for (int t = 0; t < TT; ++t) {
        // Prefetch next step's x0 line BEFORE the wait (hides the DRAM miss).
        if (w == 14 && t + 1 < TT) xnext = x0[(t + 1) * BB + lane];

        // ---- per-warp group wait (proven R8 primitive): my 8 producer CTAs
        // x 4 warps = 32 REDs per counter per step, cumulative. ----
        if (t) {
            unsigned v;
            const unsigned tgt = 32u * (unsigned)t;
            do {
                asm volatile("ld.acquire.gpu.global.u32 %0, [%1];"
                             : "=r"(v) : "l"(cons_ctr) : "memory");
            } while (v < tgt);
        }

        // ---- gate dots, register-blocked: lane (q,p) computes rows
        // 4q..4q+3 x batches 4p..4p+3. Each weight register feeds TWO
        // FFMA2s -> 2 LDS.128/k (was 4), 1 LDG.128/k, same 8 FFMA2/k.
        // L1tex per step drops below the FMA floor (R13: L1=56% bound). ----
        ulonglong2 acc2[4];
        #pragma unroll
        for (int j = 0; j < 4; ++j) acc2[j] = make_ulonglong2(0ULL, 0ULL);
        if (t) {
            const char* hbase =
                (const char*)(g_h + (size_t)(t - 1) * HB) + p * 16;
            const float* wq = W2 + q * 8;
            ulonglong2 hA[4], hB[4];
            #pragma unroll
            for (int i = 0; i < 4; ++i)
                hA[i] = *(const ulonglong2*)(hbase + (size_t)(kbeg + i) * 128);
            #pragma unroll
            for (int g = 0; g < 8; ++g) {
                ulonglong2* hc = (g & 1) ? hB : hA;
                ulonglong2* hn = (g & 1) ? hA : hB;
                if (g < 7) {
                    #pragma unroll
                    for (int i = 0; i < 4; ++i)
                        hn[i] = *(const ulonglong2*)(
                            hbase + (size_t)(kbeg + (g + 1) * 4 + i) * 128);
                }
                #pragma unroll
                for (int i = 0; i < 4; ++i) {
                    const float* wk = wq + (kbeg + g * 4 + i) * 32;
                    ulonglong2 wa = *(const ulonglong2*)(wk);      // rows 4q,4q+1
                    ulonglong2 wb = *(const ulonglong2*)(wk + 4);  // rows 4q+2,4q+3
                    fma2(acc2[0].x, wa.x, hc[i].x);
                    fma2(acc2[0].y, wa.x, hc[i].y);
                    fma2(acc2[1].x, wa.y, hc[i].x);
                    fma2(acc2[1].y, wa.y, hc[i].y);
                    fma2(acc2[2].x, wb.x, hc[i].x);
                    fma2(acc2[2].y, wb.x, hc[i].y);
                    fma2(acc2[3].x, wb.y, hc[i].x);
                    fma2(acc2[3].y, wb.y, hc[i].y);
                }
            }
        }
        float* pb = part + (t & 1) * PART_FLOATS;   // double-buffered partials
        #pragma unroll
        for (int j = 0; j < 4; ++j)
            *(ulonglong2*)(pb + (4 * q + j) * (NSEG * 32) + w * 32 + 4 * p)
                = acc2[j];
        __syncthreads();    // the ONLY CTA-wide barrier per step

        // Publish next x0 AFTER the barrier: epilogue(t-1) readers of this
        // buffer are provably done (flag chain), epilogue(t) uses the other.
        if (w == 14) x0s[((t + 1) & 1) * 32 + lane] = xnext;

        // ---- LSTM cell epilogue: 128 threads = 4 units x 32 batches.
        // Warps 4..15 run ahead into step t+1 (R13: do NOT widen this). ----
        if (tid < 128) {
            const int u = w, b = lane;
            const float xv = x0s[(t & 1) * 32 + b];
            float gs[4];
            #pragma unroll
            for (int G = 0; G < 4; ++G) {
                const int r = G * 4 + u;
                const float* pr = pb + r * (NSEG * 32) + b;
                float s = 0.0f;
                #pragma unroll
                for (int ss = 0; ss < NSEG; ++ss) s += pr[ss * 32];
                gs[G] = s + fmaf(wih[r], xv, bsum[r]);
            }
            float ig = sig_f(gs[0]);
            float fg = sig_f(gs[1]);
            float gg = tanhf(gs[2]);
            float og = sig_f(gs[3]);
            c_reg = fmaf(fg, c_reg, ig * gg);
            float hv = og * tanhf(c_reg);
            g_h[(size_t)t * HB + (j0 + u) * BB + b] = hv;

            // Per-warp publish: this warp's 32 h-STGs ordered into lane 0 by
            // __syncwarp, then ONE release-RED (32 REDs/counter/step).
            __syncwarp();
            if (b == 0)
                asm volatile("red.release.gpu.global.add.u32 [%0], 1;"
                             :: "l"(prod_ctr) : "memory");
        }
    }
}

// y[t][b] = x0 + b_lin + sum_j W_lin[j] * h[t][j][b]  — fully parallel over t,
// off the recurrence critical path. DRAM-bound: ~256MB read ≈ 35-40us.
__global__ void __launch_bounds__(256)
y_kernel(const float* __restrict__ x0,
         const float* __restrict__ W_lin,
         const float* __restrict__ b_lin,
         float* __restrict__ y)
{
    __shared__ float wl_s[HH];
    __shared__ float red[256];
    const int t = blockIdx.x, tid = threadIdx.x;
    for (int i = tid; i < HH; i += 256) wl_s[i] = W_lin[i];
    __syncthreads();
    const int b = tid & 31, jg = tid >> 5;
    const float* h = g_h + (size_t)t * HB;
    float acc = 0.0f;
    #pragma unroll 4
    for (int j = jg * 64; j < jg * 64 + 64; ++j)
        acc = fmaf(h[j * 32 + b], wl_s[j], acc);
    red[tid] = acc;
    __syncthreads();
    if (tid < 32) {
        float s = 0.0f;
        #pragma unroll
        for (int g = 0; g < 8; ++g) s += red[g * 32 + tid];
        y[t * BB + tid] = s + x0[t * BB + tid] + b_lin[0];
    }
}

extern "C" void kernel_launch(void* const* d_in, const int* in_sizes, int n_in,
                              void* d_out, int out_size)
{
    const float* x0    = (const float*)d_in[0];
    const float* W_ih  = (const float*)d_in[1];
    const float* W_hh  = (const float*)d_in[2];
    const float* b_ih  = (const float*)d_in[3];
    const float* b_hh  = (const float*)d_in[4];
    const float* W_lin = (const float*)d_in[5];
    const float* b_lin = (const float*)d_in[6];
    float* y = (float*)d_out;

    cudaFuncSetAttribute(lstm_kernel,
                         cudaFuncAttributeMaxDynamicSharedMemorySize, SMEM_BYTES);

    init_kernel<<<1, NGRP * CTR_STRIDE>>>();
    lstm_kernel<<<NCTA, NTHR, SMEM_BYTES>>>(x0, W_ih, W_hh, b_ih, b_hh);
    y_kernel<<<TT, 256>>>(x0, W_lin, b_lin, y);
}

// round 16
// speedup vs baseline: 1.1580x; 1.1580x over previous
#include <cuda_runtime.h>
#include <math.h>

// Problem constants
#define TT    4096
#define BB    32
#define HH    512
#define HB    (HH * BB)            // 16384 floats per step
#define NCTA  128
#define UNITS 4                    // hidden units per CTA
#define ROWS  16                   // gate rows per CTA
#define NTHR  512                  // 16 warps
#define NSEG  16                   // k-segments (one per warp)
#define HALFB 16                   // batches per phase
#define CTR_STRIDE 64              // 256B between counters

// Dynamic SMEM layout (floats)
#define PROW  258                  // padded partial row stride
#define PBUF  (ROWS * PROW)        // 4128 floats per half-buffer
#define SMEM_W2 (HH * ROWS * 2)    // duplicated weights: 64KB
#define SMEM_FLOATS (SMEM_W2 + 2 * PBUF + 128)   // tail: 96 used, 128 alloc
#define SMEM_BYTES  (SMEM_FLOATS * 4)            // ~98KB

// Inter-step hidden state [t][j][b] (b fastest). Distinct buffer per step.
__device__ float g_h[(size_t)TT * HB];   // 256 MB static scratch
// 16 groups x 2 halves cumulative counters. PROVEN primitives only:
// red.release.gpu.add publish + ld.acquire.gpu poll.
__device__ __align__(256) unsigned g_ctr[16 * 2 * CTR_STRIDE];

__global__ void init_kernel() {
    g_ctr[blockIdx.x * 1024 + threadIdx.x] = 0u;
}

// Packed f32x2 FMA (Blackwell packed fp32 pipe).
__device__ __forceinline__ void fma2(unsigned long long& d,
                                     unsigned long long a,
                                     unsigned long long b) {
    asm("fma.rn.f32x2 %0, %1, %2, %0;" : "+l"(d) : "l"(a), "l"(b));
}

// Sigmoid via __expf (proven). tanhf kept (R8 epilogue verbatim).
__device__ __forceinline__ float sig_f(float x) {
    return __fdividef(1.0f, 1.0f + __expf(-x));
}

__global__ void __launch_bounds__(NTHR)
lstm_kernel(const float* __restrict__ x0,     // (T,B,1)
            const float* __restrict__ W_ih,   // (4H,1)
            const float* __restrict__ W_hh,   // (4H,H) row-major
            const float* __restrict__ b_ih,   // (4H)
            const float* __restrict__ b_hh)   // (4H)
{
    extern __shared__ float sm[];
    float* W2    = sm;                      // [k][r] duplicated pairs
    float* part0 = sm + SMEM_W2;            // half-0 partials
    float* part1 = part0 + PBUF;            // half-1 partials
    float* x0s   = part1 + PBUF;            // 2 x 32 (double-buffered)
    float* wih   = x0s + 64;                // 16
    float* bsum  = wih + 16;                // 16   (96 total, 128 alloc)

    const int tid  = threadIdx.x;
    const int lane = tid & 31;
    const int w    = tid >> 5;          // warp 0..15 = k-segment
    const int rq   = lane >> 3;         // row-quad: rows 4rq..4rq+3
    const int p    = lane & 7;          // batch pair within half
    const int kbeg = w * 32;
    const int j0   = blockIdx.x * UNITS;
    const unsigned grp = blockIdx.x >> 3;   // producer group

    // Stage W_hh slice, k-major, duplicated pairs (proven R8 layout).
    for (int idx = tid; idx < ROWS * HH; idx += NTHR) {
        int r = idx & 15, k = idx >> 4;
        int grow = (r >> 2) * HH + j0 + (r & 3);
        float wv = W_hh[(size_t)grow * HH + k];
        W2[(k * ROWS + r) * 2 + 0] = wv;
        W2[(k * ROWS + r) * 2 + 1] = wv;
    }
    if (tid < ROWS) {
        int grow = (tid >> 2) * HH + j0 + (tid & 3);
        wih[tid]  = W_ih[grow];
        bsum[tid] = b_ih[grow] + b_hh[grow];
    }
    if (w == 14) x0s[lane] = x0[lane];      // x0 for t=0
    __syncthreads();

    // Cell state: threads 0..127. tid<64: half 0 (u=tid>>4, b=tid&15);
    // tid 64..127: half 1 (u=(tid-64)>>4, b=16+((tid-64)&15)).
    float c_reg = 0.0f;
    float xnext = 0.0f;

    for (int t = 0; t < TT; ++t) {
        // Prefetch next step's x0 line once per step, before any wait.
        if (w == 14 && t + 1 < TT) xnext = x0[(t + 1) * BB + lane];

        #pragma unroll
        for (int hf = 0; hf < 2; ++hf) {
            float* pb = hf ? part1 : part0;

            // ---- group wait for h(t-1, this half). With phase pipelining
            // the publish happened ~1 phase (~1600cyc) ago -> first-try hit.
            if (t) {
                const unsigned* cc = g_ctr + (w * 2 + hf) * CTR_STRIDE;
                const unsigned tgt = 16u * (unsigned)t;  // 8 CTAs x 2 warps
                unsigned v;
                do {
                    asm volatile("ld.acquire.gpu.global.u32 %0, [%1];"
                                 : "=r"(v) : "l"(cc) : "memory");
                } while (v < tgt);
            }

            // ---- gate dots: 16 rows x this half's 16 batches, 32 k's.
            // Lane (rq,p): rows 4rq..4rq+3, batches hf*16+2p..2p+1.
            // Per k: 2 LDS.128 (W) + 1 LDG.64 (h, broadcast x4) + 4 FFMA2.
            unsigned long long a0 = 0, a1 = 0, a2 = 0, a3 = 0;
            if (t) {
                const char* hbase = (const char*)(g_h + (size_t)(t - 1) * HB)
                                    + hf * 64 + p * 8;
                const float* wq = W2 + rq * 8;
                unsigned long long hA[4], hB[4];
                #pragma unroll
                for (int i = 0; i < 4; ++i)
                    hA[i] = *(const unsigned long long*)(
                        hbase + (size_t)(kbeg + i) * 128);
                #pragma unroll
                for (int g = 0; g < 8; ++g) {
                    unsigned long long* hc = (g & 1) ? hB : hA;
                    unsigned long long* hn = (g & 1) ? hA : hB;
                    if (g < 7) {
                        #pragma unroll
                        for (int i = 0; i < 4; ++i)
                            hn[i] = *(const unsigned long long*)(
                                hbase + (size_t)(kbeg + (g + 1) * 4 + i) * 128);
                    }
                    #pragma unroll
                    for (int i = 0; i < 4; ++i) {
                        const float* wk = wq + (kbeg + g * 4 + i) * 32;
                        ulonglong2 wa = *(const ulonglong2*)(wk);     // r 4rq,4rq+1
                        ulonglong2 wb = *(const ulonglong2*)(wk + 4); // r 4rq+2,4rq+3
                        fma2(a0, wa.x, hc[i]);
                        fma2(a1, wa.y, hc[i]);
                        fma2(a2, wb.x, hc[i]);
                        fma2(a3, wb.y, hc[i]);
                    }
                }
            }
            // partials[r][seg=w][b within half]
            *(unsigned long long*)(pb + (4 * rq + 0) * PROW + w * 16 + 2 * p) = a0;
            *(unsigned long long*)(pb + (4 * rq + 1) * PROW + w * 16 + 2 * p) = a1;
            *(unsigned long long*)(pb + (4 * rq + 2) * PROW + w * 16 + 2 * p) = a2;
            *(unsigned long long*)(pb + (4 * rq + 3) * PROW + w * 16 + 2 * p) = a3;
            __syncthreads();   // one BAR per phase

            // Publish next x0 after phase-0 BAR: all readers of that slot
            // (epilogues of step t-1) are provably done by now.
            if (hf == 0 && w == 14) x0s[((t + 1) & 1) * 32 + lane] = xnext;

            // ---- cell epilogue for this half: warps 2hf..2hf+1 (64 thr).
            // Other 14 warps run ahead into the next phase's poll+mainloop.
            if ((tid >> 6) == hf) {
                const int local = tid & 63;
                const int u  = local >> 4;
                const int bb = local & 15;
                const int batch = hf * HALFB + bb;
                const float xv = x0s[(t & 1) * 32 + batch];
                float gs[4];
                #pragma unroll
                for (int G = 0; G < 4; ++G) {
                    const int r = G * 4 + u;
                    const float* pr = pb + r * PROW + bb;
                    float s = 0.0f;
                    #pragma unroll
                    for (int ss = 0; ss < NSEG; ++ss) s += pr[ss * 16];
                    gs[G] = s + fmaf(wih[r], xv, bsum[r]);
                }
                float ig = sig_f(gs[0]);
                float fg = sig_f(gs[1]);
                float gg = tanhf(gs[2]);
                float og = sig_f(gs[3]);
                c_reg = fmaf(fg, c_reg, ig * gg);
                float hv = og * tanhf(c_reg);
                g_h[(size_t)t * HB + (j0 + u) * BB + batch] = hv;

                // Warp's h-STGs ordered into lane 0, then ONE release-RED.
                __syncwarp();
                if ((tid & 31) == 0)
                    asm volatile("red.release.gpu.global.add.u32 [%0], 1;"
                                 :: "l"(g_ctr + (grp * 2 + (unsigned)hf)
                                        * CTR_STRIDE) : "memory");
            }
        }
    }
}

// y[t][b] = x0 + b_lin + sum_j W_lin[j] * h[t][j][b] — off the critical path.
__global__ void __launch_bounds__(256)
y_kernel(const float* __restrict__ x0,
         const float* __restrict__ W_lin,
         const float* __restrict__ b_lin,
         float* __restrict__ y)
{
    __shared__ float wl_s[HH];
    __shared__ float red[256];
    const int t = blockIdx.x, tid = threadIdx.x;
    for (int i = tid; i < HH; i += 256) wl_s[i] = W_lin[i];
    __syncthreads();
    const int b = tid & 31, jg = tid >> 5;
    const float* h = g_h + (size_t)t * HB;
    float acc = 0.0f;
    #pragma unroll 4
    for (int j = jg * 64; j < jg * 64 + 64; ++j)
        acc = fmaf(h[j * 32 + b], wl_s[j], acc);
    red[tid] = acc;
    __syncthreads();
    if (tid < 32) {
        float s = 0.0f;
        #pragma unroll
        for (int g = 0; g < 8; ++g) s += red[g * 32 + tid];
        y[t * BB + tid] = s + x0[t * BB + tid] + b_lin[0];
    }
}

extern "C" void kernel_launch(void* const* d_in, const int* in_sizes, int n_in,
                              void* d_out, int out_size)
{
    const float* x0    = (const float*)d_in[0];
    const float* W_ih  = (const float*)d_in[1];
    const float* W_hh  = (const float*)d_in[2];
    const float* b_ih  = (const float*)d_in[3];
    const float* b_hh  = (const float*)d_in[4];
    const float* W_lin = (const float*)d_in[5];
    const float* b_lin = (const float*)d_in[6];
    float* y = (float*)d_out;

    cudaFuncSetAttribute(lstm_kernel,
                         cudaFuncAttributeMaxDynamicSharedMemorySize, SMEM_BYTES);

    init_kernel<<<2, 1024>>>();   // 2048 counter words
    lstm_kernel<<<NCTA, NTHR, SMEM_BYTES>>>(x0, W_ih, W_hh, b_ih, b_hh);
    y_kernel<<<TT, 256>>>(x0, W_lin, b_lin, y);
}

// round 17
// speedup vs baseline: 1.5176x; 1.3105x over previous
#include <cuda_runtime.h>
#include <math.h>

// Problem constants
#define TT    4096
#define BB    32
#define HH    512
#define HB    (HH * BB)            // 16384 floats per step
#define NCTA  128                  // persistent CTAs, all wave-1 resident
#define UNITS 4                    // hidden units per CTA
#define ROWS  16                   // gate rows per CTA (4 gates x 4 units)
#define NTHR  512                  // 16 warps
#define NSEG  16                   // k-segments per row (one per warp)
#define NGRP  16                   // barrier groups (8 CTAs each)
#define CTR_STRIDE 64              // 256B between counters -> distinct LTS lines

// Asymmetric k-split: epilogue warps (0-3) get 8 k's, warps 4-15 get 40.
// 4*8 + 12*40 = 512. Epilogue work then overlaps the long mainloops instead
// of serializing after them at the step barrier.
#define KE 8
#define KO 40

// Dynamic SMEM layout (floats)
#define PART_FLOATS (ROWS * NSEG * BB)          // 8192 floats = 32KB per buffer
#define SMEM_W2     (HH * ROWS * 2)             // duplicated weights: 64KB
#define SMEM_FLOATS (SMEM_W2 + 2 * PART_FLOATS + 128)
#define SMEM_BYTES  (SMEM_FLOATS * 4)           // ~131.5KB

// Inter-step hidden state [t][j][b] (b fastest). Distinct buffer per step
// => one-way producer/consumer sync, no anti-dependency.
__device__ float g_h[(size_t)TT * HB];   // 256 MB static scratch
// 16 cumulative group counters (group g = CTAs 8g..8g+7), padded 256B apart.
// PROVEN primitives only: red.release.gpu.add publish + ld.acquire.gpu poll.
__device__ __align__(256) unsigned g_ctr16[NGRP * CTR_STRIDE];

__global__ void init_kernel() { g_ctr16[threadIdx.x] = 0u; }  // 1024 threads

// Packed f32x2 FMA (Blackwell packed fp32 pipe).
__device__ __forceinline__ void fma2(unsigned long long& d,
                                     unsigned long long a,
                                     unsigned long long b) {
    asm("fma.rn.f32x2 %0, %1, %2, %0;" : "+l"(d) : "l"(a), "l"(b));
}

// Sigmoid via __expf (proven R2..R16). tanhf kept (R8 epilogue verbatim;
// isolate exactly one change this round).
__device__ __forceinline__ float sig_f(float x) {
    return __fdividef(1.0f, 1.0f + __expf(-x));
}

__device__ __forceinline__ void poll_ctr(const unsigned* c, unsigned tgt) {
    unsigned v;
    do {
        asm volatile("ld.acquire.gpu.global.u32 %0, [%1];"
                     : "=r"(v) : "l"(c) : "memory");
    } while (v < tgt);
}

// The proven R8 group-of-4 distance-1 pipelined dot block, parameterized by
// compile-time group count NG (2 or 10) — all indices constant after unroll.
#define GATE_DOTS(NG)                                                         \
    {                                                                         \
        const unsigned long long* hq =                                        \
            (const unsigned long long*)(g_h + (size_t)(t - 1) * HB) + p;      \
        const float* wbase = W2 + kh * 16;                                    \
        unsigned long long hA[4], hB[4];                                      \
        _Pragma("unroll")                                                     \
        for (int i = 0; i < 4; ++i) hA[i] = hq[(size_t)(kbeg + i) * 16];      \
        _Pragma("unroll")                                                     \
        for (int g = 0; g < (NG); ++g) {                                      \
            unsigned long long* hc = (g & 1) ? hB : hA;                       \
            unsigned long long* hn = (g & 1) ? hA : hB;                       \
            if (g < (NG) - 1) {                                               \
                _Pragma("unroll")                                             \
                for (int i = 0; i < 4; ++i)                                   \
                    hn[i] = hq[(size_t)(kbeg + (g + 1) * 4 + i) * 16];        \
            }                                                                 \
            _Pragma("unroll")                                                 \
            for (int i = 0; i < 4; ++i) {                                     \
                const float* wk = wbase + (kbeg + g * 4 + i) * 32;            \
                ulonglong2 w01 = *(const ulonglong2*)(wk);                    \
                ulonglong2 w23 = *(const ulonglong2*)(wk + 4);                \
                ulonglong2 w45 = *(const ulonglong2*)(wk + 8);                \
                ulonglong2 w67 = *(const ulonglong2*)(wk + 12);               \
                fma2(acc[0], w01.x, hc[i]); fma2(acc[1], w01.y, hc[i]);       \
                fma2(acc[2], w23.x, hc[i]); fma2(acc[3], w23.y, hc[i]);       \
                fma2(acc[4], w45.x, hc[i]); fma2(acc[5], w45.y, hc[i]);       \
                fma2(acc[6], w67.x, hc[i]); fma2(acc[7], w67.y, hc[i]);       \
            }                                                                 \
        }                                                                     \
    }

__global__ void __launch_bounds__(NTHR)
lstm_kernel(const float* __restrict__ x0,     // (T,B,1)
            const float* __restrict__ W_ih,   // (4H,1)
            const float* __restrict__ W_hh,   // (4H,H) row-major
            const float* __restrict__ b_ih,   // (4H)
            const float* __restrict__ b_hh)   // (4H)
{
    extern __shared__ float sm[];
    float* W2   = sm;                        // [k][r] duplicated pairs
    float* part = sm + SMEM_W2;              // 2 x [r][seg][b]
    float* x0s  = part + 2 * PART_FLOATS;    // 2 x 32 (double-buffered)
    float* wih  = x0s + 64;                  // 16
    float* bsum = wih + 16;                  // 16

    const int tid  = threadIdx.x;
    const int lane = tid & 31;
    const int w    = tid >> 5;           // warp 0..15 = k-segment
    const int kh   = lane >> 4;          // row-half: rows 8*kh .. 8*kh+7
    const int p    = lane & 15;          // batch pair -> batches 2p, 2p+1
    // Asymmetric k ranges: warps 0-3: [8w, 8w+8); warps 4-15: [32+40(w-4), +40)
    const int kbeg = (w < 4) ? (w * KE) : (32 + (w - 4) * KO);
    const int kcnt = (w < 4) ? KE : KO;
    const int j0   = blockIdx.x * UNITS;
    // Consumer counters: unit range [kbeg, kbeg+kcnt) -> 1 or 2 groups of 32.
    const int glo = kbeg >> 5;
    const int ghi = (kbeg + kcnt - 1) >> 5;
    const unsigned* cons_lo = g_ctr16 + glo * CTR_STRIDE;
    const unsigned* cons_hi = g_ctr16 + ghi * CTR_STRIDE;
    // Counter this CTA PRODUCES into: group blockIdx.x>>3.
    unsigned* prod_ctr = g_ctr16 + (blockIdx.x >> 3) * CTR_STRIDE;

    // Stage W_hh slice, k-major, duplicated pairs: W2[(k*16+r)*2 + {0,1}] = w.
    for (int idx = tid; idx < ROWS * HH; idx += NTHR) {
        int r = idx & 15, k = idx >> 4;
        int grow = (r >> 2) * HH + j0 + (r & 3);   // gate*512 + j0 + unit
        float wv = W_hh[(size_t)grow * HH + k];
        W2[(k * ROWS + r) * 2 + 0] = wv;
        W2[(k * ROWS + r) * 2 + 1] = wv;
    }
    if (tid < ROWS) {
        int grow = (tid >> 2) * HH + j0 + (tid & 3);
        wih[tid]  = W_ih[grow];
        bsum[tid] = b_ih[grow] + b_hh[grow];
    }
    if (w == 14) x0s[lane] = x0[lane];           // x0 for t=0
    __syncthreads();

    float c_reg = 0.0f;     // epilogue threads (tid<128): unit w, batch lane
    float xnext = 0.0f;

    for (int t = 0; t < TT; ++t) {
        // Prefetch next step's x0 line BEFORE the wait (hides the DRAM miss).
        if (w == 14 && t + 1 < TT) xnext = x0[(t + 1) * BB + lane];

        // ---- per-warp group wait (proven primitives): poll the 1-2 group
        // counters covering this warp's k range; 32 REDs/counter/step. ----
        if (t) {
            const unsigned tgt = 32u * (unsigned)t;
            poll_ctr(cons_lo, tgt);
            if (ghi != glo) poll_ctr(cons_hi, tgt);
        }

        // ---- gate dots: all 16 rows for this warp's k slice (8 or 40 k's).
        unsigned long long acc[8] = {0, 0, 0, 0, 0, 0, 0, 0};
        if (t) {
            if (w < 4) GATE_DOTS(2)       // epilogue warps: short mainloop
            else       GATE_DOTS(10)      // others: long mainloop
        }
        float* pb = part + (t & 1) * PART_FLOATS;   // double-buffered partials
        #pragma unroll
        for (int j = 0; j < 8; ++j)
            *(unsigned long long*)(pb + ((8 * kh + j) * NSEG + w) * 32 + 2 * p)
                = acc[j];
        __syncthreads();    // the ONLY CTA-wide barrier per step

        // Publish next x0 AFTER the barrier: epilogue(t-1) readers of this
        // buffer are provably done (flag chain), epilogue(t) uses the other.
        if (w == 14) x0s[((t + 1) & 1) * 32 + lane] = xnext;

        // ---- LSTM cell epilogue: 128 threads = 4 units x 32 batches.
        // These warps had the SHORT mainloop, so this work overlaps the
        // other warps' long mainloops instead of extending the step.
        if (tid < 128) {
            const int u = w, b = lane;
            const float xv = x0s[(t & 1) * 32 + b];
            float gs[4];
            #pragma unroll
            for (int G = 0; G < 4; ++G) {
                const int r = G * 4 + u;
                const float* pr = pb + r * (NSEG * 32) + b;
                float s = 0.0f;
                #pragma unroll
                for (int ss = 0; ss < NSEG; ++ss) s += pr[ss * 32];
                gs[G] = s + fmaf(wih[r], xv, bsum[r]);
            }
            float ig = sig_f(gs[0]);
            float fg = sig_f(gs[1]);
            float gg = tanhf(gs[2]);
            float og = sig_f(gs[3]);
            c_reg = fmaf(fg, c_reg, ig * gg);
            float hv = og * tanhf(c_reg);
            g_h[(size_t)t * HB + (j0 + u) * BB + b] = hv;

            // Per-warp publish: this warp's 32 h-STGs ordered into lane 0 by
            // __syncwarp, then ONE release-RED (32 REDs/counter/step).
            __syncwarp();
            if (b == 0)
                asm volatile("red.release.gpu.global.add.u32 [%0], 1;"
                             :: "l"(prod_ctr) : "memory");
        }
    }
}

// y[t][b] = x0 + b_lin + sum_j W_lin[j] * h[t][j][b]  — fully parallel over t,
// off the recurrence critical path. DRAM-bound: ~256MB read ≈ 35-40us.
__global__ void __launch_bounds__(256)
y_kernel(const float* __restrict__ x0,
         const float* __restrict__ W_lin,
         const float* __restrict__ b_lin,
         float* __restrict__ y)
{
    __shared__ float wl_s[HH];
    __shared__ float red[256];
    const int t = blockIdx.x, tid = threadIdx.x;
    for (int i = tid; i < HH; i += 256) wl_s[i] = W_lin[i];
    __syncthreads();
    const int b = tid & 31, jg = tid >> 5;
    const float* h = g_h + (size_t)t * HB;
    float acc = 0.0f;
    #pragma unroll 4
    for (int j = jg * 64; j < jg * 64 + 64; ++j)
        acc = fmaf(h[j * 32 + b], wl_s[j], acc);
    red[tid] = acc;
    __syncthreads();
    if (tid < 32) {
        float s = 0.0f;
        #pragma unroll
        for (int g = 0; g < 8; ++g) s += red[g * 32 + tid];
        y[t * BB + tid] = s + x0[t * BB + tid] + b_lin[0];
    }
}

extern "C" void kernel_launch(void* const* d_in, const int* in_sizes, int n_in,
                              void* d_out, int out_size)
{
    const float* x0    = (const float*)d_in[0];
    const float* W_ih  = (const float*)d_in[1];
    const float* W_hh  = (const float*)d_in[2];
    const float* b_ih  = (const float*)d_in[3];
    const float* b_hh  = (const float*)d_in[4];
    const float* W_lin = (const float*)d_in[5];
    const float* b_lin = (const float*)d_in[6];
    float* y = (float*)d_out;

    cudaFuncSetAttribute(lstm_kernel,
                         cudaFuncAttributeMaxDynamicSharedMemorySize, SMEM_BYTES);

    init_kernel<<<1, NGRP * CTR_STRIDE>>>();
    lstm_kernel<<<NCTA, NTHR, SMEM_BYTES>>>(x0, W_ih, W_hh, b_ih, b_hh);
    y_kernel<<<TT, 256>>>(x0, W_lin, b_lin, y);
}